// round 12
// baseline (speedup 1.0000x reference)
#include <cuda_runtime.h>
#include <cuda_bf16.h>
#include <math.h>
#include <stdint.h>

#define Bdim 8
#define Ldim 1024
#define Hdim 8
#define Edim 64
#define BM 64
#define BN 64
#define NTH 256
#define ROWB 144              // 72 bf16 per row: conflict-free ldmatrix
#define TILEB 9216            // 64 rows * 144 B
#define STAGEB (4 * TILEB)    // khi,klo,vhi,vlo per stage = 36864 B

// SMEM: stage0 at 0, stage1 at STAGEB, then tab/crow
#define OFF_TAB   73728
#define OFF_CROW  77824
#define SMEM_TOTAL 78080
// Q staging overlays stage1 (used only in prologue, before stage1's first load)
#define OFF_QHI 36864
#define OFF_QLO 46080
// epilogue scratch overlays stage0
#define OFF_OSCR 0
#define OFF_LSCR 18432

#define TOT8 (Bdim * Ldim * Hdim * Edim / 8)

// split-bf16 K/V in [b][h][i][e] layout
__device__ __nv_bfloat16 gKhi[Bdim * Hdim * Ldim * Edim];
__device__ __nv_bfloat16 gKlo[Bdim * Hdim * Ldim * Edim];
__device__ __nv_bfloat16 gVhi[Bdim * Hdim * Ldim * Edim];
__device__ __nv_bfloat16 gVlo[Bdim * Hdim * Ldim * Edim];

__device__ __forceinline__ uint32_t smem_u32(const void* p) {
    uint32_t a;
    asm("{ .reg .u64 t; cvta.to.shared.u64 t, %1; cvt.u32.u64 %0, t; }" : "=r"(a) : "l"(p));
    return a;
}
__device__ __forceinline__ void ldsm_x4(uint32_t* r, uint32_t addr) {
    asm volatile("ldmatrix.sync.aligned.m8n8.x4.shared.b16 {%0,%1,%2,%3}, [%4];"
                 : "=r"(r[0]), "=r"(r[1]), "=r"(r[2]), "=r"(r[3]) : "r"(addr));
}
__device__ __forceinline__ void ldsm_x2(uint32_t& r0, uint32_t& r1, uint32_t addr) {
    asm volatile("ldmatrix.sync.aligned.m8n8.x2.shared.b16 {%0,%1}, [%2];"
                 : "=r"(r0), "=r"(r1) : "r"(addr));
}
__device__ __forceinline__ void ldsm_x4t(uint32_t* r, uint32_t addr) {
    asm volatile("ldmatrix.sync.aligned.m8n8.x4.trans.shared.b16 {%0,%1,%2,%3}, [%4];"
                 : "=r"(r[0]), "=r"(r[1]), "=r"(r[2]), "=r"(r[3]) : "r"(addr));
}
__device__ __forceinline__ void mma16816(float4& d, const uint32_t* a, uint32_t b0, uint32_t b1) {
    asm volatile("mma.sync.aligned.m16n8k16.row.col.f32.bf16.bf16.f32 "
                 "{%0,%1,%2,%3}, {%4,%5,%6,%7}, {%8,%9}, {%0,%1,%2,%3};"
                 : "+f"(d.x), "+f"(d.y), "+f"(d.z), "+f"(d.w)
                 : "r"(a[0]), "r"(a[1]), "r"(a[2]), "r"(a[3]), "r"(b0), "r"(b1));
}
__device__ __forceinline__ void cp_async16(uint32_t saddr, const void* gptr) {
    asm volatile("cp.async.cg.shared.global [%0], [%1], 16;" :: "r"(saddr), "l"(gptr) : "memory");
}
__device__ __forceinline__ void split2(float a, float b, uint32_t& hi, uint32_t& lo) {
    const __nv_bfloat16 ha = __float2bfloat16_rn(a), hb = __float2bfloat16_rn(b);
    const float ra = a - __bfloat162float(ha), rb = b - __bfloat162float(hb);
    hi = (uint32_t)__bfloat16_as_ushort(ha) | ((uint32_t)__bfloat16_as_ushort(hb) << 16);
    lo = (uint32_t)__bfloat16_as_ushort(__float2bfloat16_rn(ra))
       | ((uint32_t)__bfloat16_as_ushort(__float2bfloat16_rn(rb)) << 16);
}
__device__ __forceinline__ float softplusf(float x) {
    return (x > 20.0f) ? x : log1pf(expf(x));
}

// ---- pre-pass: fp32 K,V [b][i][h][e] -> split-bf16 [b][h][i][e], 8 elems/thread ----
__global__ __launch_bounds__(256)
void prepass(const float* __restrict__ Kg, const float* __restrict__ Vg) {
    const int c = blockIdx.x * 256 + threadIdx.x;
    if (c >= TOT8) return;
    const int ec8 = c & 7;
    const int h   = (c >> 3) & 7;
    const int i   = (c >> 6) & 1023;
    const int b   = c >> 16;
    const size_t src = (((size_t)(b * Ldim + i)) * Hdim + h) * Edim + ec8 * 8;
    const size_t dst = (((size_t)(b * Hdim + h)) * Ldim + i) * Edim + ec8 * 8;
    uint32_t h0, l0, h1, l1, h2, l2, h3, l3;
    {
        const float4 a0 = *(const float4*)(Kg + src);
        const float4 a1 = *(const float4*)(Kg + src + 4);
        split2(a0.x, a0.y, h0, l0); split2(a0.z, a0.w, h1, l1);
        split2(a1.x, a1.y, h2, l2); split2(a1.z, a1.w, h3, l3);
        *(uint4*)(gKhi + dst) = make_uint4(h0, h1, h2, h3);
        *(uint4*)(gKlo + dst) = make_uint4(l0, l1, l2, l3);
    }
    {
        const float4 a0 = *(const float4*)(Vg + src);
        const float4 a1 = *(const float4*)(Vg + src + 4);
        split2(a0.x, a0.y, h0, l0); split2(a0.z, a0.w, h1, l1);
        split2(a1.x, a1.y, h2, l2); split2(a1.z, a1.w, h3, l3);
        *(uint4*)(gVhi + dst) = make_uint4(h0, h1, h2, h3);
        *(uint4*)(gVlo + dst) = make_uint4(l0, l1, l2, l3);
    }
}

__global__ __launch_bounds__(NTH, 2)
void fullattn_main(const float* __restrict__ Qg, const float* __restrict__ attn_tau,
                   const float* __restrict__ exp_para, const float* __restrict__ tau,
                   float* __restrict__ Out)
{
    extern __shared__ char smem[];
    const uint32_t sb = smem_u32(smem);
    const int tid = threadIdx.x;
    const int wid = tid >> 5, lane = tid & 31;
    const int strip = wid >> 1;            // 0..3: 16-row q strip
    const int jh = wid & 1;                // key-half of the 64-wide tile
    const int bh = blockIdx.y, b = bh >> 3, h = bh & 7;
    const int i0 = blockIdx.x * BM;
    const int ibase = strip * 16;
    const size_t kvbase = (size_t)bh * Ldim * Edim;

    // ---- prefetch tile 0 into stage0 (overlaps with all prologue work) ----
    for (int idx = tid; idx < 512; idx += NTH) {
        const int r = idx >> 3, c = idx & 7;
        const size_t src = kvbase + (size_t)r * Edim + c * 8;
        const uint32_t doff = r * ROWB + c * 16;
        cp_async16(sb + 0 * TILEB + doff, gKhi + src);
        cp_async16(sb + 1 * TILEB + doff, gKlo + src);
        cp_async16(sb + 2 * TILEB + doff, gVhi + src);
        cp_async16(sb + 3 * TILEB + doff, gVlo + src);
    }
    asm volatile("cp.async.commit_group;" ::: "memory");

    float* tab  = (float*)(smem + OFF_TAB);
    float* crow = (float*)(smem + OFF_CROW);
    {
        const float p = softplusf(exp_para[0]);
        for (int d = tid; d < Ldim; d += NTH)
            tab[d] = (d == 0) ? 0.0f : powf((float)d, p);
        if (tid < BM) {
            const int i = i0 + tid;
            crow[tid] = 1.0f / (softplusf(attn_tau[i]) * softplusf(tau[i]));
        }
    }

    // ---- Q tile (64 x 64): scale 1/8, split, stage in stage1 region ----
    for (int idx = tid; idx < BM * (Edim / 4); idx += NTH) {
        const int r = idx >> 4, ec = (idx & 15) << 2;
        float4 v = *(const float4*)(Qg + ((size_t)(b * Ldim + i0 + r) * Hdim + h) * Edim + ec);
        v.x *= 0.125f; v.y *= 0.125f; v.z *= 0.125f; v.w *= 0.125f;
        uint32_t h0, l0, h1, l1;
        split2(v.x, v.y, h0, l0);
        split2(v.z, v.w, h1, l1);
        const int off = r * ROWB + ec * 2;
        *(uint32_t*)(smem + OFF_QHI + off)     = h0;
        *(uint32_t*)(smem + OFF_QHI + off + 4) = h1;
        *(uint32_t*)(smem + OFF_QLO + off)     = l0;
        *(uint32_t*)(smem + OFF_QLO + off + 4) = l1;
    }
    __syncthreads();

    uint32_t aqh[4][4], aql[4][4];
    {
        const int arow = ibase + (lane & 15);
        #pragma unroll
        for (int s = 0; s < 4; ++s) {
            const int col = 16 * s + 8 * (lane >> 4);
            ldsm_x4(aqh[s], sb + OFF_QHI + arow * ROWB + col * 2);
            ldsm_x4(aql[s], sb + OFF_QLO + arow * ROWB + col * 2);
        }
    }
    __syncthreads();   // stage1 region free for prefetches

    float4 oacc[8];
    #pragma unroll
    for (int t = 0; t < 8; ++t) oacc[t] = make_float4(0.f, 0.f, 0.f, 0.f);
    float lr0 = 0.0f, lr1 = 0.0f;

    const int qr  = lane >> 2;
    const int qc  = lane & 3;
    const float ci0 = crow[ibase + qr];
    const float ci1 = crow[ibase + qr + 8];
    const int gi0 = i0 + ibase + qr;
    const int gi1 = gi0 + 8;
    const int jhb = jh * 32;               // warp's key offset inside the 64-tile

    for (int kt = 0; kt < Ldim / BN; ++kt) {
        const uint32_t cur = (kt & 1) ? STAGEB : 0;
        const uint32_t nxt = cur ^ STAGEB;

        // ---- prefetch tile kt+1 into the other stage, then wait for tile kt ----
        if (kt < Ldim / BN - 1) {
            const int jt = (kt + 1) * BN;
            for (int idx = tid; idx < 512; idx += NTH) {
                const int r = idx >> 3, c = idx & 7;
                const size_t src = kvbase + (size_t)(jt + r) * Edim + c * 8;
                const uint32_t doff = nxt + r * ROWB + c * 16;
                cp_async16(sb + doff,             gKhi + src);
                cp_async16(sb + doff + TILEB,     gKlo + src);
                cp_async16(sb + doff + 2 * TILEB, gVhi + src);
                cp_async16(sb + doff + 3 * TILEB, gVlo + src);
            }
            asm volatile("cp.async.commit_group;" ::: "memory");
            asm volatile("cp.async.wait_group 1;" ::: "memory");
        } else {
            asm volatile("cp.async.wait_group 0;" ::: "memory");
        }
        __syncthreads();

        // ---- S = (Q/8) K^T : 4 n-tiles x 4 k-steps x 3 terms ----
        float4 sacc[4];
        #pragma unroll
        for (int t = 0; t < 4; ++t) sacc[t] = make_float4(0.f, 0.f, 0.f, 0.f);
        const int krow_off = (lane & 7) * ROWB;
        const int kcol_off = 16 * ((lane >> 3) & 1);
        #pragma unroll
        for (int t = 0; t < 4; ++t) {
            const uint32_t rbase = cur + (jhb + t * 8) * ROWB + krow_off;
            #pragma unroll
            for (int s = 0; s < 4; ++s) {
                const int coff = s * 32 + kcol_off;
                uint32_t bh0, bh1, bl0, bl1;
                ldsm_x2(bh0, bh1, sb + rbase + coff);
                ldsm_x2(bl0, bl1, sb + rbase + TILEB + coff);
                mma16816(sacc[t], aqh[s], bh0, bh1);
                mma16816(sacc[t], aqh[s], bl0, bl1);
                mma16816(sacc[t], aql[s], bh0, bh1);
            }
        }

        // ---- fused: bias + exp + split -> PV MMAs ----
        const int j0 = kt * BN;
        const int vrow_off = ((lane & 7) + 8 * ((lane >> 3) & 1)) * ROWB;
        const int vcol_off = 16 * (lane >> 4);
        #pragma unroll
        for (int sj = 0; sj < 2; ++sj) {
            uint32_t ah[4], al[4];
            #pragma unroll
            for (int u = 0; u < 2; ++u) {
                const int t = 2 * sj + u;
                const int jA = j0 + jhb + t * 8 + 2 * qc;
                int d00 = gi0 - jA,     d01 = gi0 - jA - 1;
                int d10 = gi1 - jA,     d11 = gi1 - jA - 1;
                d00 = (d00 < 0) ? -d00 : d00;  d01 = (d01 < 0) ? -d01 : d01;
                d10 = (d10 < 0) ? -d10 : d10;  d11 = (d11 < 0) ? -d11 : d11;
                const float p0 = __expf(sacc[t].x - tab[d00] * ci0);
                const float p1 = __expf(sacc[t].y - tab[d01] * ci0);
                const float p2 = __expf(sacc[t].z - tab[d10] * ci1);
                const float p3 = __expf(sacc[t].w - tab[d11] * ci1);
                lr0 += p0 + p1;
                lr1 += p2 + p3;
                split2(p0, p1, ah[2 * u],     al[2 * u]);
                split2(p2, p3, ah[2 * u + 1], al[2 * u + 1]);
            }
            const uint32_t rbase = cur + 2 * TILEB + (jhb + sj * 16) * ROWB + vrow_off;
            #pragma unroll
            for (int tp = 0; tp < 4; ++tp) {
                const int coff = tp * 32 + vcol_off;
                uint32_t vh[4], vl[4];
                ldsm_x4t(vh, sb + rbase + coff);
                ldsm_x4t(vl, sb + rbase + TILEB + coff);
                mma16816(oacc[2*tp],     ah, vh[0], vh[1]);
                mma16816(oacc[2*tp + 1], ah, vh[2], vh[3]);
                mma16816(oacc[2*tp],     ah, vl[0], vl[1]);
                mma16816(oacc[2*tp + 1], ah, vl[2], vl[3]);
                mma16816(oacc[2*tp],     al, vh[0], vh[1]);
                mma16816(oacc[2*tp + 1], al, vh[2], vh[3]);
            }
        }
        __syncthreads();   // all warps done reading cur before kt+2's prefetch reuses it
    }

    // ---- combine j-halves, normalize, store ----
    #pragma unroll
    for (int sh = 1; sh < 4; sh <<= 1) {
        lr0 += __shfl_xor_sync(0xffffffffu, lr0, sh);
        lr1 += __shfl_xor_sync(0xffffffffu, lr1, sh);
    }
    float* oscr = (float*)(smem + OFF_OSCR);
    float* lscr = (float*)(smem + OFF_LSCR);
    if (jh == 1) {
        float* dst = oscr + (strip * 32 + lane) * 33;
        #pragma unroll
        for (int t = 0; t < 8; ++t) {
            dst[4 * t]     = oacc[t].x;
            dst[4 * t + 1] = oacc[t].y;
            dst[4 * t + 2] = oacc[t].z;
            dst[4 * t + 3] = oacc[t].w;
        }
        lscr[(strip * 32 + lane) * 2]     = lr0;
        lscr[(strip * 32 + lane) * 2 + 1] = lr1;
    }
    __syncthreads();
    if (jh == 0) {
        const float* src = oscr + (strip * 32 + lane) * 33;
        const float inv0 = 1.0f / (lr0 + lscr[(strip * 32 + lane) * 2]);
        const float inv1 = 1.0f / (lr1 + lscr[(strip * 32 + lane) * 2 + 1]);
        const long ob0 = ((long)(b * Ldim + gi0) * Hdim + h) * Edim;
        const long ob1 = ((long)(b * Ldim + gi1) * Hdim + h) * Edim;
        #pragma unroll
        for (int te = 0; te < 8; ++te) {
            const int e0 = te * 8 + 2 * qc;
            *(float2*)(Out + ob0 + e0) = make_float2((oacc[te].x + src[4*te])     * inv0,
                                                     (oacc[te].y + src[4*te + 1]) * inv0);
            *(float2*)(Out + ob1 + e0) = make_float2((oacc[te].z + src[4*te + 2]) * inv1,
                                                     (oacc[te].w + src[4*te + 3]) * inv1);
        }
    }
}

extern "C" void kernel_launch(void* const* d_in, const int* in_sizes, int n_in,
                              void* d_out, int out_size) {
    const float* Q        = (const float*)d_in[0];
    const float* K        = (const float*)d_in[1];
    const float* V        = (const float*)d_in[2];
    // d_in[3] = attn_mask (unused, mask_flag=False)
    const float* attn_tau = (const float*)d_in[4];
    const float* exp_para = (const float*)d_in[5];
    const float* tau      = (const float*)d_in[6];
    float* out = (float*)d_out;

    prepass<<<TOT8 / 256, 256>>>(K, V);
    cudaFuncSetAttribute(fullattn_main, cudaFuncAttributeMaxDynamicSharedMemorySize, SMEM_TOTAL);
    dim3 grid(Ldim / BM, Bdim * Hdim);   // (16, 64)
    fullattn_main<<<grid, NTH, SMEM_TOTAL>>>(Q, attn_tau, exp_para, tau, out);
}

// round 13
// speedup vs baseline: 1.2871x; 1.2871x over previous
#include <cuda_runtime.h>
#include <cuda_fp16.h>
#include <math.h>
#include <stdint.h>

#define Bdim 8
#define Ldim 1024
#define Hdim 8
#define Edim 64
#define BM 64
#define BN 64
#define NTH 256
#define ROWB 144              // 72 fp16 per row: conflict-free ldmatrix
#define TILEB 9216            // 64 rows * 144 B
#define STAGEB (4 * TILEB)    // khi,klo,vhi,vlo per stage = 36864 B

// SMEM: stage0 at 0, stage1 at STAGEB, then tab/crow
#define OFF_TAB   73728
#define OFF_CROW  77824
#define SMEM_TOTAL 78080
// Q staging overlays stage1 (prologue only)
#define OFF_QS 36864
// epilogue scratch overlays stage0
#define OFF_OSCR 0
#define OFF_LSCR 18432

#define TOT8 (Bdim * Ldim * Hdim * Edim / 8)

// split-fp16 K/V in [b][h][i][e] layout
__device__ __half gKhi[Bdim * Hdim * Ldim * Edim];
__device__ __half gKlo[Bdim * Hdim * Ldim * Edim];
__device__ __half gVhi[Bdim * Hdim * Ldim * Edim];
__device__ __half gVlo[Bdim * Hdim * Ldim * Edim];

__device__ __forceinline__ uint32_t smem_u32(const void* p) {
    uint32_t a;
    asm("{ .reg .u64 t; cvta.to.shared.u64 t, %1; cvt.u32.u64 %0, t; }" : "=r"(a) : "l"(p));
    return a;
}
__device__ __forceinline__ void ldsm_x4(uint32_t* r, uint32_t addr) {
    asm volatile("ldmatrix.sync.aligned.m8n8.x4.shared.b16 {%0,%1,%2,%3}, [%4];"
                 : "=r"(r[0]), "=r"(r[1]), "=r"(r[2]), "=r"(r[3]) : "r"(addr));
}
__device__ __forceinline__ void ldsm_x2(uint32_t& r0, uint32_t& r1, uint32_t addr) {
    asm volatile("ldmatrix.sync.aligned.m8n8.x2.shared.b16 {%0,%1}, [%2];"
                 : "=r"(r0), "=r"(r1) : "r"(addr));
}
__device__ __forceinline__ void ldsm_x4t(uint32_t* r, uint32_t addr) {
    asm volatile("ldmatrix.sync.aligned.m8n8.x4.trans.shared.b16 {%0,%1,%2,%3}, [%4];"
                 : "=r"(r[0]), "=r"(r[1]), "=r"(r[2]), "=r"(r[3]) : "r"(addr));
}
// D += A * B : m16n8k16 fp16 -> f32
__device__ __forceinline__ void mma16816h(float4& d, const uint32_t* a, uint32_t b0, uint32_t b1) {
    asm volatile("mma.sync.aligned.m16n8k16.row.col.f32.f16.f16.f32 "
                 "{%0,%1,%2,%3}, {%4,%5,%6,%7}, {%8,%9}, {%0,%1,%2,%3};"
                 : "+f"(d.x), "+f"(d.y), "+f"(d.z), "+f"(d.w)
                 : "r"(a[0]), "r"(a[1]), "r"(a[2]), "r"(a[3]), "r"(b0), "r"(b1));
}
__device__ __forceinline__ void cp_async16(uint32_t saddr, const void* gptr) {
    asm volatile("cp.async.cg.shared.global [%0], [%1], 16;" :: "r"(saddr), "l"(gptr) : "memory");
}
__device__ __forceinline__ uint32_t cvt2h(float a, float b) {   // pack lo=a, hi=b
    const __half ha = __float2half_rn(a), hb = __float2half_rn(b);
    return (uint32_t)__half_as_ushort(ha) | ((uint32_t)__half_as_ushort(hb) << 16);
}
__device__ __forceinline__ void split2h(float a, float b, uint32_t& hi, uint32_t& lo) {
    const __half ha = __float2half_rn(a), hb = __float2half_rn(b);
    const float ra = a - __half2float(ha), rb = b - __half2float(hb);
    hi = (uint32_t)__half_as_ushort(ha) | ((uint32_t)__half_as_ushort(hb) << 16);
    lo = (uint32_t)__half_as_ushort(__float2half_rn(ra))
       | ((uint32_t)__half_as_ushort(__float2half_rn(rb)) << 16);
}
__device__ __forceinline__ float softplusf(float x) {
    return (x > 20.0f) ? x : log1pf(expf(x));
}

// ---- pre-pass: fp32 K,V [b][i][h][e] -> split-fp16 [b][h][i][e], 8 elems/thread ----
__global__ __launch_bounds__(256)
void prepass(const float* __restrict__ Kg, const float* __restrict__ Vg) {
    const int c = blockIdx.x * 256 + threadIdx.x;
    if (c >= TOT8) return;
    const int ec8 = c & 7;
    const int h   = (c >> 3) & 7;
    const int i   = (c >> 6) & 1023;
    const int b   = c >> 16;
    const size_t src = (((size_t)(b * Ldim + i)) * Hdim + h) * Edim + ec8 * 8;
    const size_t dst = (((size_t)(b * Hdim + h)) * Ldim + i) * Edim + ec8 * 8;
    uint32_t h0, l0, h1, l1, h2, l2, h3, l3;
    {
        const float4 a0 = *(const float4*)(Kg + src);
        const float4 a1 = *(const float4*)(Kg + src + 4);
        split2h(a0.x, a0.y, h0, l0); split2h(a0.z, a0.w, h1, l1);
        split2h(a1.x, a1.y, h2, l2); split2h(a1.z, a1.w, h3, l3);
        *(uint4*)(gKhi + dst) = make_uint4(h0, h1, h2, h3);
        *(uint4*)(gKlo + dst) = make_uint4(l0, l1, l2, l3);
    }
    {
        const float4 a0 = *(const float4*)(Vg + src);
        const float4 a1 = *(const float4*)(Vg + src + 4);
        split2h(a0.x, a0.y, h0, l0); split2h(a0.z, a0.w, h1, l1);
        split2h(a1.x, a1.y, h2, l2); split2h(a1.z, a1.w, h3, l3);
        *(uint4*)(gVhi + dst) = make_uint4(h0, h1, h2, h3);
        *(uint4*)(gVlo + dst) = make_uint4(l0, l1, l2, l3);
    }
}

__global__ __launch_bounds__(NTH, 2)
void fullattn_main(const float* __restrict__ Qg, const float* __restrict__ attn_tau,
                   const float* __restrict__ exp_para, const float* __restrict__ tau,
                   float* __restrict__ Out)
{
    extern __shared__ char smem[];
    const uint32_t sb = smem_u32(smem);
    const int tid = threadIdx.x;
    const int wid = tid >> 5, lane = tid & 31;
    const int strip = wid >> 1;            // 0..3: 16-row q strip
    const int jh = wid & 1;                // key-half of the 64-wide tile
    const int bh = blockIdx.y, b = bh >> 3, h = bh & 7;
    const int i0 = blockIdx.x * BM;
    const int ibase = strip * 16;
    const size_t kvbase = (size_t)bh * Ldim * Edim;

    // ---- prefetch tile 0 into stage0 (overlaps all prologue work) ----
    for (int idx = tid; idx < 512; idx += NTH) {
        const int r = idx >> 3, c = idx & 7;
        const size_t src = kvbase + (size_t)r * Edim + c * 8;
        const uint32_t doff = r * ROWB + c * 16;
        cp_async16(sb + 0 * TILEB + doff, gKhi + src);
        cp_async16(sb + 1 * TILEB + doff, gKlo + src);
        cp_async16(sb + 2 * TILEB + doff, gVhi + src);
        cp_async16(sb + 3 * TILEB + doff, gVlo + src);
    }
    asm volatile("cp.async.commit_group;" ::: "memory");

    float* tab  = (float*)(smem + OFF_TAB);
    float* crow = (float*)(smem + OFF_CROW);
    {
        const float p = softplusf(exp_para[0]);
        for (int d = tid; d < Ldim; d += NTH)
            tab[d] = (d == 0) ? 0.0f : powf((float)d, p);
        if (tid < BM) {
            const int i = i0 + tid;
            crow[tid] = 1.0f / (softplusf(attn_tau[i]) * softplusf(tau[i]));
        }
    }

    // ---- Q tile (64 x 64): scale 1/8 (exact), single fp16, stage in stage1 ----
    for (int idx = tid; idx < BM * (Edim / 4); idx += NTH) {
        const int r = idx >> 4, ec = (idx & 15) << 2;
        float4 v = *(const float4*)(Qg + ((size_t)(b * Ldim + i0 + r) * Hdim + h) * Edim + ec);
        const int off = r * ROWB + ec * 2;
        *(uint32_t*)(smem + OFF_QS + off)     = cvt2h(v.x * 0.125f, v.y * 0.125f);
        *(uint32_t*)(smem + OFF_QS + off + 4) = cvt2h(v.z * 0.125f, v.w * 0.125f);
    }
    __syncthreads();

    uint32_t aq[4][4];
    {
        const int arow = ibase + (lane & 15);
        #pragma unroll
        for (int s = 0; s < 4; ++s) {
            const int col = 16 * s + 8 * (lane >> 4);
            ldsm_x4(aq[s], sb + OFF_QS + arow * ROWB + col * 2);
        }
    }
    __syncthreads();   // stage1 region free for prefetches

    float4 oacc[8];
    #pragma unroll
    for (int t = 0; t < 8; ++t) oacc[t] = make_float4(0.f, 0.f, 0.f, 0.f);
    float lr0 = 0.0f, lr1 = 0.0f;

    const int qr  = lane >> 2;
    const int qc  = lane & 3;
    const float ci0 = crow[ibase + qr];
    const float ci1 = crow[ibase + qr + 8];
    const int gi0 = i0 + ibase + qr;
    const int gi1 = gi0 + 8;
    const int jhb = jh * 32;               // warp's key offset inside the 64-tile

    for (int kt = 0; kt < Ldim / BN; ++kt) {
        const uint32_t cur = (kt & 1) ? STAGEB : 0;
        const uint32_t nxt = cur ^ STAGEB;

        // ---- prefetch tile kt+1 into the other stage, then wait for tile kt ----
        if (kt < Ldim / BN - 1) {
            const int jt = (kt + 1) * BN;
            for (int idx = tid; idx < 512; idx += NTH) {
                const int r = idx >> 3, c = idx & 7;
                const size_t src = kvbase + (size_t)(jt + r) * Edim + c * 8;
                const uint32_t doff = nxt + r * ROWB + c * 16;
                cp_async16(sb + doff,             gKhi + src);
                cp_async16(sb + doff + TILEB,     gKlo + src);
                cp_async16(sb + doff + 2 * TILEB, gVhi + src);
                cp_async16(sb + doff + 3 * TILEB, gVlo + src);
            }
            asm volatile("cp.async.commit_group;" ::: "memory");
            asm volatile("cp.async.wait_group 1;" ::: "memory");
        } else {
            asm volatile("cp.async.wait_group 0;" ::: "memory");
        }
        __syncthreads();

        // ---- S = (Q/8) K^T : 4 n-tiles x 4 k-steps x 2 terms (fp16) ----
        float4 sacc[4];
        #pragma unroll
        for (int t = 0; t < 4; ++t) sacc[t] = make_float4(0.f, 0.f, 0.f, 0.f);
        const int krow_off = (lane & 7) * ROWB;
        const int kcol_off = 16 * ((lane >> 3) & 1);
        #pragma unroll
        for (int t = 0; t < 4; ++t) {
            const uint32_t rbase = cur + (jhb + t * 8) * ROWB + krow_off;
            #pragma unroll
            for (int s = 0; s < 4; ++s) {
                const int coff = s * 32 + kcol_off;
                uint32_t bh0, bh1, bl0, bl1;
                ldsm_x2(bh0, bh1, sb + rbase + coff);
                ldsm_x2(bl0, bl1, sb + rbase + TILEB + coff);
                mma16816h(sacc[t], aq[s], bh0, bh1);
                mma16816h(sacc[t], aq[s], bl0, bl1);
            }
        }

        // ---- fused: bias + exp + cvt-to-fp16 -> PV MMAs ----
        const int j0 = kt * BN;
        const int vrow_off = ((lane & 7) + 8 * ((lane >> 3) & 1)) * ROWB;
        const int vcol_off = 16 * (lane >> 4);
        #pragma unroll
        for (int sj = 0; sj < 2; ++sj) {
            uint32_t ah[4];
            #pragma unroll
            for (int u = 0; u < 2; ++u) {
                const int t = 2 * sj + u;
                const int jA = j0 + jhb + t * 8 + 2 * qc;
                int d00 = gi0 - jA,     d01 = gi0 - jA - 1;
                int d10 = gi1 - jA,     d11 = gi1 - jA - 1;
                d00 = (d00 < 0) ? -d00 : d00;  d01 = (d01 < 0) ? -d01 : d01;
                d10 = (d10 < 0) ? -d10 : d10;  d11 = (d11 < 0) ? -d11 : d11;
                const float p0 = __expf(sacc[t].x - tab[d00] * ci0);
                const float p1 = __expf(sacc[t].y - tab[d01] * ci0);
                const float p2 = __expf(sacc[t].z - tab[d10] * ci1);
                const float p3 = __expf(sacc[t].w - tab[d11] * ci1);
                lr0 += p0 + p1;
                lr1 += p2 + p3;
                ah[2 * u]     = cvt2h(p0, p1);
                ah[2 * u + 1] = cvt2h(p2, p3);
            }
            const uint32_t rbase = cur + 2 * TILEB + (jhb + sj * 16) * ROWB + vrow_off;
            #pragma unroll
            for (int tp = 0; tp < 4; ++tp) {
                const int coff = tp * 32 + vcol_off;
                uint32_t vh[4], vl[4];
                ldsm_x4t(vh, sb + rbase + coff);
                ldsm_x4t(vl, sb + rbase + TILEB + coff);
                mma16816h(oacc[2*tp],     ah, vh[0], vh[1]);
                mma16816h(oacc[2*tp + 1], ah, vh[2], vh[3]);
                mma16816h(oacc[2*tp],     ah, vl[0], vl[1]);
                mma16816h(oacc[2*tp + 1], ah, vl[2], vl[3]);
            }
        }
        __syncthreads();   // all warps done reading cur before kt+2's prefetch reuses it
    }

    // ---- combine j-halves, normalize, store ----
    #pragma unroll
    for (int sh = 1; sh < 4; sh <<= 1) {
        lr0 += __shfl_xor_sync(0xffffffffu, lr0, sh);
        lr1 += __shfl_xor_sync(0xffffffffu, lr1, sh);
    }
    float* oscr = (float*)(smem + OFF_OSCR);
    float* lscr = (float*)(smem + OFF_LSCR);
    if (jh == 1) {
        float* dst = oscr + (strip * 32 + lane) * 33;
        #pragma unroll
        for (int t = 0; t < 8; ++t) {
            dst[4 * t]     = oacc[t].x;
            dst[4 * t + 1] = oacc[t].y;
            dst[4 * t + 2] = oacc[t].z;
            dst[4 * t + 3] = oacc[t].w;
        }
        lscr[(strip * 32 + lane) * 2]     = lr0;
        lscr[(strip * 32 + lane) * 2 + 1] = lr1;
    }
    __syncthreads();
    if (jh == 0) {
        const float* src = oscr + (strip * 32 + lane) * 33;
        const float inv0 = 1.0f / (lr0 + lscr[(strip * 32 + lane) * 2]);
        const float inv1 = 1.0f / (lr1 + lscr[(strip * 32 + lane) * 2 + 1]);
        const long ob0 = ((long)(b * Ldim + gi0) * Hdim + h) * Edim;
        const long ob1 = ((long)(b * Ldim + gi1) * Hdim + h) * Edim;
        #pragma unroll
        for (int te = 0; te < 8; ++te) {
            const int e0 = te * 8 + 2 * qc;
            *(float2*)(Out + ob0 + e0) = make_float2((oacc[te].x + src[4*te])     * inv0,
                                                     (oacc[te].y + src[4*te + 1]) * inv0);
            *(float2*)(Out + ob1 + e0) = make_float2((oacc[te].z + src[4*te + 2]) * inv1,
                                                     (oacc[te].w + src[4*te + 3]) * inv1);
        }
    }
}

extern "C" void kernel_launch(void* const* d_in, const int* in_sizes, int n_in,
                              void* d_out, int out_size) {
    const float* Q        = (const float*)d_in[0];
    const float* K        = (const float*)d_in[1];
    const float* V        = (const float*)d_in[2];
    // d_in[3] = attn_mask (unused, mask_flag=False)
    const float* attn_tau = (const float*)d_in[4];
    const float* exp_para = (const float*)d_in[5];
    const float* tau      = (const float*)d_in[6];
    float* out = (float*)d_out;

    prepass<<<TOT8 / 256, 256>>>(K, V);
    cudaFuncSetAttribute(fullattn_main, cudaFuncAttributeMaxDynamicSharedMemorySize, SMEM_TOTAL);
    dim3 grid(Ldim / BM, Bdim * Hdim);   // (16, 64)
    fullattn_main<<<grid, NTH, SMEM_TOTAL>>>(Q, attn_tau, exp_para, tau, out);
}

// round 15
// speedup vs baseline: 1.5434x; 1.1992x over previous
#include <cuda_runtime.h>
#include <cuda_fp16.h>
#include <math.h>
#include <stdint.h>

#define Bdim 8
#define Ldim 1024
#define Hdim 8
#define Edim 64
#define BM 64
#define BN 64
#define NTH 256
#define ROWB 144              // 72 fp16 per row: conflict-free ldmatrix
#define TILEB 9216            // 64 rows * 144 B
#define STAGEB (3 * TILEB)    // khi, klo, vhi per stage = 27648 B

// SMEM: stage0 at 0, stage1 at STAGEB, then tab/crow
#define OFF_TAB   55296
#define OFF_CROW  59392
#define SMEM_TOTAL 59648
// Q staging overlays stage1 (prologue only)
#define OFF_QS STAGEB
// epilogue scratch overlays stage0
#define OFF_OSCR 0
#define OFF_LSCR 18432

#define TOT8 (Bdim * Ldim * Hdim * Edim / 8)

// K split-fp16, V single-fp16, [b][h][i][e] layout
__device__ __half gKhi[Bdim * Hdim * Ldim * Edim];
__device__ __half gKlo[Bdim * Hdim * Ldim * Edim];
__device__ __half gVs [Bdim * Hdim * Ldim * Edim];

__device__ __forceinline__ uint32_t smem_u32(const void* p) {
    uint32_t a;
    asm("{ .reg .u64 t; cvta.to.shared.u64 t, %1; cvt.u32.u64 %0, t; }" : "=r"(a) : "l"(p));
    return a;
}
__device__ __forceinline__ void ldsm_x4(uint32_t* r, uint32_t addr) {
    asm volatile("ldmatrix.sync.aligned.m8n8.x4.shared.b16 {%0,%1,%2,%3}, [%4];"
                 : "=r"(r[0]), "=r"(r[1]), "=r"(r[2]), "=r"(r[3]) : "r"(addr));
}
__device__ __forceinline__ void ldsm_x2(uint32_t& r0, uint32_t& r1, uint32_t addr) {
    asm volatile("ldmatrix.sync.aligned.m8n8.x2.shared.b16 {%0,%1}, [%2];"
                 : "=r"(r0), "=r"(r1) : "r"(addr));
}
__device__ __forceinline__ void ldsm_x4t(uint32_t* r, uint32_t addr) {
    asm volatile("ldmatrix.sync.aligned.m8n8.x4.trans.shared.b16 {%0,%1,%2,%3}, [%4];"
                 : "=r"(r[0]), "=r"(r[1]), "=r"(r[2]), "=r"(r[3]) : "r"(addr));
}
// D += A * B : m16n8k16 fp16 -> f32
__device__ __forceinline__ void mma16816h(float4& d, const uint32_t* a, uint32_t b0, uint32_t b1) {
    asm volatile("mma.sync.aligned.m16n8k16.row.col.f32.f16.f16.f32 "
                 "{%0,%1,%2,%3}, {%4,%5,%6,%7}, {%8,%9}, {%0,%1,%2,%3};"
                 : "+f"(d.x), "+f"(d.y), "+f"(d.z), "+f"(d.w)
                 : "r"(a[0]), "r"(a[1]), "r"(a[2]), "r"(a[3]), "r"(b0), "r"(b1));
}
__device__ __forceinline__ void cp_async16(uint32_t saddr, const void* gptr) {
    asm volatile("cp.async.cg.shared.global [%0], [%1], 16;" :: "r"(saddr), "l"(gptr) : "memory");
}
__device__ __forceinline__ uint32_t cvt2h(float a, float b) {   // pack lo=a, hi=b
    const __half ha = __float2half_rn(a), hb = __float2half_rn(b);
    return (uint32_t)__half_as_ushort(ha) | ((uint32_t)__half_as_ushort(hb) << 16);
}
__device__ __forceinline__ void split2h(float a, float b, uint32_t& hi, uint32_t& lo) {
    const __half ha = __float2half_rn(a), hb = __float2half_rn(b);
    const float ra = a - __half2float(ha), rb = b - __half2float(hb);
    hi = (uint32_t)__half_as_ushort(ha) | ((uint32_t)__half_as_ushort(hb) << 16);
    lo = (uint32_t)__half_as_ushort(__float2half_rn(ra))
       | ((uint32_t)__half_as_ushort(__float2half_rn(rb)) << 16);
}
__device__ __forceinline__ float softplusf(float x) {
    return (x > 20.0f) ? x : log1pf(expf(x));
}

// ---- pre-pass: fp32 K,V [b][i][h][e] -> K split / V single fp16 [b][h][i][e] ----
__global__ __launch_bounds__(256)
void prepass(const float* __restrict__ Kg, const float* __restrict__ Vg) {
    const int c = blockIdx.x * 256 + threadIdx.x;
    if (c >= TOT8) return;
    const int ec8 = c & 7;
    const int h   = (c >> 3) & 7;
    const int i   = (c >> 6) & 1023;
    const int b   = c >> 16;
    const size_t src = (((size_t)(b * Ldim + i)) * Hdim + h) * Edim + ec8 * 8;
    const size_t dst = (((size_t)(b * Hdim + h)) * Ldim + i) * Edim + ec8 * 8;
    {
        uint32_t h0, l0, h1, l1, h2, l2, h3, l3;
        const float4 a0 = *(const float4*)(Kg + src);
        const float4 a1 = *(const float4*)(Kg + src + 4);
        split2h(a0.x, a0.y, h0, l0); split2h(a0.z, a0.w, h1, l1);
        split2h(a1.x, a1.y, h2, l2); split2h(a1.z, a1.w, h3, l3);
        *(uint4*)(gKhi + dst) = make_uint4(h0, h1, h2, h3);
        *(uint4*)(gKlo + dst) = make_uint4(l0, l1, l2, l3);
    }
    {
        const float4 a0 = *(const float4*)(Vg + src);
        const float4 a1 = *(const float4*)(Vg + src + 4);
        *(uint4*)(gVs + dst) = make_uint4(cvt2h(a0.x, a0.y), cvt2h(a0.z, a0.w),
                                          cvt2h(a1.x, a1.y), cvt2h(a1.z, a1.w));
    }
}

__global__ __launch_bounds__(NTH, 2)
void fullattn_main(const float* __restrict__ Qg, const float* __restrict__ attn_tau,
                   const float* __restrict__ exp_para, const float* __restrict__ tau,
                   float* __restrict__ Out)
{
    extern __shared__ char smem[];
    const uint32_t sb = smem_u32(smem);
    const int tid = threadIdx.x;
    const int wid = tid >> 5, lane = tid & 31;
    const int strip = wid >> 1;            // 0..3: 16-row q strip
    const int jh = wid & 1;                // key-half of the 64-wide tile
    const int bh = blockIdx.y, b = bh >> 3, h = bh & 7;
    const int i0 = blockIdx.x * BM;
    const int ibase = strip * 16;
    const size_t kvbase = (size_t)bh * Ldim * Edim;

    // ---- prefetch tile 0 into stage0 (overlaps all prologue work) ----
    for (int idx = tid; idx < 512; idx += NTH) {
        const int r = idx >> 3, c = idx & 7;
        const size_t src = kvbase + (size_t)r * Edim + c * 8;
        const uint32_t doff = r * ROWB + c * 16;
        cp_async16(sb + 0 * TILEB + doff, gKhi + src);
        cp_async16(sb + 1 * TILEB + doff, gKlo + src);
        cp_async16(sb + 2 * TILEB + doff, gVs  + src);
    }
    asm volatile("cp.async.commit_group;" ::: "memory");

    float* tab  = (float*)(smem + OFF_TAB);
    float* crow = (float*)(smem + OFF_CROW);
    {
        const float p = softplusf(exp_para[0]);
        for (int d = tid; d < Ldim; d += NTH)
            tab[d] = (d == 0) ? 0.0f : powf((float)d, p);
        if (tid < BM) {
            const int i = i0 + tid;
            crow[tid] = 1.0f / (softplusf(attn_tau[i]) * softplusf(tau[i]));
        }
    }

    // ---- Q tile (64 x 64): scale 1/8 (exact), single fp16, stage in stage1 ----
    for (int idx = tid; idx < BM * (Edim / 4); idx += NTH) {
        const int r = idx >> 4, ec = (idx & 15) << 2;
        float4 v = *(const float4*)(Qg + ((size_t)(b * Ldim + i0 + r) * Hdim + h) * Edim + ec);
        const int off = r * ROWB + ec * 2;
        *(uint32_t*)(smem + OFF_QS + off)     = cvt2h(v.x * 0.125f, v.y * 0.125f);
        *(uint32_t*)(smem + OFF_QS + off + 4) = cvt2h(v.z * 0.125f, v.w * 0.125f);
    }
    __syncthreads();

    uint32_t aq[4][4];
    {
        const int arow = ibase + (lane & 15);
        #pragma unroll
        for (int s = 0; s < 4; ++s) {
            const int col = 16 * s + 8 * (lane >> 4);
            ldsm_x4(aq[s], sb + OFF_QS + arow * ROWB + col * 2);
        }
    }
    __syncthreads();   // stage1 region free for prefetches

    float4 oacc[8];
    #pragma unroll
    for (int t = 0; t < 8; ++t) oacc[t] = make_float4(0.f, 0.f, 0.f, 0.f);
    float lr0 = 0.0f, lr1 = 0.0f;

    const int qr  = lane >> 2;
    const int qc  = lane & 3;
    const float ci0 = crow[ibase + qr];
    const float ci1 = crow[ibase + qr + 8];
    const int gi0 = i0 + ibase + qr;
    const int gi1 = gi0 + 8;
    const int jhb = jh * 32;               // warp's key offset inside the 64-tile

    for (int kt = 0; kt < Ldim / BN; ++kt) {
        const uint32_t cur = (kt & 1) ? STAGEB : 0;
        const uint32_t nxt = cur ^ STAGEB;

        // ---- prefetch tile kt+1 into the other stage, then wait for tile kt ----
        if (kt < Ldim / BN - 1) {
            const int jt = (kt + 1) * BN;
            for (int idx = tid; idx < 512; idx += NTH) {
                const int r = idx >> 3, c = idx & 7;
                const size_t src = kvbase + (size_t)(jt + r) * Edim + c * 8;
                const uint32_t doff = nxt + r * ROWB + c * 16;
                cp_async16(sb + doff,             gKhi + src);
                cp_async16(sb + doff + TILEB,     gKlo + src);
                cp_async16(sb + doff + 2 * TILEB, gVs  + src);
            }
            asm volatile("cp.async.commit_group;" ::: "memory");
            asm volatile("cp.async.wait_group 1;" ::: "memory");
        } else {
            asm volatile("cp.async.wait_group 0;" ::: "memory");
        }
        __syncthreads();

        // ---- S = (Q/8) K^T : 4 n-tiles x 4 k-steps x 2 terms (fp16) ----
        float4 sacc[4];
        #pragma unroll
        for (int t = 0; t < 4; ++t) sacc[t] = make_float4(0.f, 0.f, 0.f, 0.f);
        const int krow_off = (lane & 7) * ROWB;
        const int kcol_off = 16 * ((lane >> 3) & 1);
        #pragma unroll
        for (int t = 0; t < 4; ++t) {
            const uint32_t rbase = cur + (jhb + t * 8) * ROWB + krow_off;
            #pragma unroll
            for (int s = 0; s < 4; ++s) {
                const int coff = s * 32 + kcol_off;
                uint32_t bh0, bh1, bl0, bl1;
                ldsm_x2(bh0, bh1, sb + rbase + coff);
                ldsm_x2(bl0, bl1, sb + rbase + TILEB + coff);
                mma16816h(sacc[t], aq[s], bh0, bh1);
                mma16816h(sacc[t], aq[s], bl0, bl1);
            }
        }

        // ---- fused: bias + exp + cvt-to-fp16 -> PV MMAs (V single) ----
        const int j0 = kt * BN;
        const int vrow_off = ((lane & 7) + 8 * ((lane >> 3) & 1)) * ROWB;
        const int vcol_off = 16 * (lane >> 4);
        #pragma unroll
        for (int sj = 0; sj < 2; ++sj) {
            uint32_t ah[4];
            #pragma unroll
            for (int u = 0; u < 2; ++u) {
                const int t = 2 * sj + u;
                const int jA = j0 + jhb + t * 8 + 2 * qc;
                int d00 = gi0 - jA,     d01 = gi0 - jA - 1;
                int d10 = gi1 - jA,     d11 = gi1 - jA - 1;
                d00 = (d00 < 0) ? -d00 : d00;  d01 = (d01 < 0) ? -d01 : d01;
                d10 = (d10 < 0) ? -d10 : d10;  d11 = (d11 < 0) ? -d11 : d11;
                const float p0 = __expf(sacc[t].x - tab[d00] * ci0);
                const float p1 = __expf(sacc[t].y - tab[d01] * ci0);
                const float p2 = __expf(sacc[t].z - tab[d10] * ci1);
                const float p3 = __expf(sacc[t].w - tab[d11] * ci1);
                lr0 += p0 + p1;
                lr1 += p2 + p3;
                ah[2 * u]     = cvt2h(p0, p1);
                ah[2 * u + 1] = cvt2h(p2, p3);
            }
            const uint32_t rbase = cur + 2 * TILEB + (jhb + sj * 16) * ROWB + vrow_off;
            #pragma unroll
            for (int tp = 0; tp < 4; ++tp) {
                uint32_t vh[4];
                ldsm_x4t(vh, sb + rbase + tp * 32 + vcol_off);
                mma16816h(oacc[2*tp],     ah, vh[0], vh[1]);
                mma16816h(oacc[2*tp + 1], ah, vh[2], vh[3]);
            }
        }
        __syncthreads();   // all warps done reading cur before kt+2's prefetch reuses it
    }

    // ---- combine j-halves, normalize, store ----
    #pragma unroll
    for (int sh = 1; sh < 4; sh <<= 1) {
        lr0 += __shfl_xor_sync(0xffffffffu, lr0, sh);
        lr1 += __shfl_xor_sync(0xffffffffu, lr1, sh);
    }
    float* oscr = (float*)(smem + OFF_OSCR);
    float* lscr = (float*)(smem + OFF_LSCR);
    if (jh == 1) {
        float* dst = oscr + (strip * 32 + lane) * 33;
        #pragma unroll
        for (int t = 0; t < 8; ++t) {
            dst[4 * t]     = oacc[t].x;
            dst[4 * t + 1] = oacc[t].y;
            dst[4 * t + 2] = oacc[t].z;
            dst[4 * t + 3] = oacc[t].w;
        }
        lscr[(strip * 32 + lane) * 2]     = lr0;
        lscr[(strip * 32 + lane) * 2 + 1] = lr1;
    }
    __syncthreads();
    if (jh == 0) {
        const float* src = oscr + (strip * 32 + lane) * 33;
        const float inv0 = 1.0f / (lr0 + lscr[(strip * 32 + lane) * 2]);
        const float inv1 = 1.0f / (lr1 + lscr[(strip * 32 + lane) * 2 + 1]);
        const long ob0 = ((long)(b * Ldim + gi0) * Hdim + h) * Edim;
        const long ob1 = ((long)(b * Ldim + gi1) * Hdim + h) * Edim;
        #pragma unroll
        for (int te = 0; te < 8; ++te) {
            const int e0 = te * 8 + 2 * qc;
            *(float2*)(Out + ob0 + e0) = make_float2((oacc[te].x + src[4*te])     * inv0,
                                                     (oacc[te].y + src[4*te + 1]) * inv0);
            *(float2*)(Out + ob1 + e0) = make_float2((oacc[te].z + src[4*te + 2]) * inv1,
                                                     (oacc[te].w + src[4*te + 3]) * inv1);
        }
    }
}

extern "C" void kernel_launch(void* const* d_in, const int* in_sizes, int n_in,
                              void* d_out, int out_size) {
    const float* Q        = (const float*)d_in[0];
    const float* K        = (const float*)d_in[1];
    const float* V        = (const float*)d_in[2];
    // d_in[3] = attn_mask (unused, mask_flag=False)
    const float* attn_tau = (const float*)d_in[4];
    const float* exp_para = (const float*)d_in[5];
    const float* tau      = (const float*)d_in[6];
    float* out = (float*)d_out;

    prepass<<<TOT8 / 256, 256>>>(K, V);
    cudaFuncSetAttribute(fullattn_main, cudaFuncAttributeMaxDynamicSharedMemorySize, SMEM_TOTAL);
    dim3 grid(Ldim / BM, Bdim * Hdim);   // (16, 64)
    fullattn_main<<<grid, NTH, SMEM_TOTAL>>>(Q, attn_tau, exp_para, tau, out);
}